// round 3
// baseline (speedup 1.0000x reference)
#include <cuda_runtime.h>

// Problem constants
#define B_   16
#define OUT_ 1024
#define IN_  2048
#define RPB  4                       // rows per block
#define NV4  (IN_ / 4)               // 512 float4 per row

__global__ __launch_bounds__(256)
void led_kernel(const int*   __restrict__ x,       // (B,1,IN) int32
                const float* __restrict__ weight,  // (OUT,IN)
                const float* __restrict__ trace,   // (B,OUT,IN)
                const float* __restrict__ delay,   // (B,OUT,IN)
                const float* __restrict__ dinit,   // constant tensor; only [0] read
                const float* __restrict__ dt_p,
                const float* __restrict__ tau_p,
                const float* __restrict__ alpha_p,
                float* __restrict__ pot,           // (B,OUT)
                float* __restrict__ folded)        // (B,OUT,IN) flat
{
    const int row0 = blockIdx.x * RPB;   // 4 consecutive rows, same batch b
    const int b    = row0 >> 10;         // / OUT_

    const float k     = __ldg(dt_p) / __ldg(tau_p);
    const float alpha = __ldg(alpha_p);
    const float d0    = __ldg(dinit);    // constant-valued tensor
    const float c1    = 1.0f - k;        // t_new = c1*t + (k*alpha)*xf
    const float c0    = k * alpha;

    const int j0 = threadIdx.x;
    const int j1 = threadIdx.x + 256;

    // x is shared by all RPB rows (same batch): load once.
    const int4* __restrict__ x4 = (const int4*)(x + (long)b * IN_);
    const int4 xA = __ldg(x4 + j0);
    const int4 xB = __ldg(x4 + j1);

    const float xfA0 = (float)xA.x, xfA1 = (float)xA.y, xfA2 = (float)xA.z, xfA3 = (float)xA.w;
    const float xfB0 = (float)xB.x, xfB1 = (float)xB.y, xfB2 = (float)xB.z, xfB3 = (float)xB.w;

    // spike threshold: delay == 1 - d0*x  (exact integer-valued floats)
    const float thA0 = fmaf(-d0, xfA0, 1.0f), thA1 = fmaf(-d0, xfA1, 1.0f);
    const float thA2 = fmaf(-d0, xfA2, 1.0f), thA3 = fmaf(-d0, xfA3, 1.0f);
    const float thB0 = fmaf(-d0, xfB0, 1.0f), thB1 = fmaf(-d0, xfB1, 1.0f);
    const float thB2 = fmaf(-d0, xfB2, 1.0f), thB3 = fmaf(-d0, xfB3, 1.0f);

    // trace injection term per element: c0*xf
    const float inA0 = c0 * xfA0, inA1 = c0 * xfA1, inA2 = c0 * xfA2, inA3 = c0 * xfA3;
    const float inB0 = c0 * xfB0, inB1 = c0 * xfB1, inB2 = c0 * xfB2, inB3 = c0 * xfB3;

    float acc[RPB];

    #pragma unroll
    for (int r = 0; r < RPB; r++) {
        const int  row  = row0 + r;
        const long base = (long)row * IN_;
        const int  o    = row & (OUT_ - 1);

        const float4* __restrict__ tr4 = (const float4*)(trace  + base);
        const float4* __restrict__ dl4 = (const float4*)(delay  + base);
        const float4* __restrict__ w4  = (const float4*)(weight + (long)o * IN_);
        float4*       __restrict__ ou4 = (float4*)(folded + base);

        float4 t0 = __ldcs(tr4 + j0);
        float4 t1 = __ldcs(tr4 + j1);
        float4 dA = __ldcs(dl4 + j0);
        float4 dB = __ldcs(dl4 + j1);
        float4 w0 = __ldg (w4  + j0);
        float4 w1 = __ldg (w4  + j1);

        // trace update + streaming store
        t0.x = fmaf(c1, t0.x, inA0);
        t0.y = fmaf(c1, t0.y, inA1);
        t0.z = fmaf(c1, t0.z, inA2);
        t0.w = fmaf(c1, t0.w, inA3);
        __stcs(ou4 + j0, t0);

        t1.x = fmaf(c1, t1.x, inB0);
        t1.y = fmaf(c1, t1.y, inB1);
        t1.z = fmaf(c1, t1.z, inB2);
        t1.w = fmaf(c1, t1.w, inB3);
        __stcs(ou4 + j1, t1);

        // spike-masked weight accumulation
        float a = 0.0f;
        if (dA.x == thA0) a += w0.x;
        if (dA.y == thA1) a += w0.y;
        if (dA.z == thA2) a += w0.z;
        if (dA.w == thA3) a += w0.w;
        if (dB.x == thB0) a += w1.x;
        if (dB.y == thB1) a += w1.y;
        if (dB.z == thB2) a += w1.z;
        if (dB.w == thB3) a += w1.w;
        acc[r] = a;
    }

    // Reduce all RPB accumulators: warp shuffle, then cross-warp via smem.
    #pragma unroll
    for (int r = 0; r < RPB; r++) {
        #pragma unroll
        for (int off = 16; off > 0; off >>= 1)
            acc[r] += __shfl_xor_sync(0xFFFFFFFFu, acc[r], off);
    }

    __shared__ float ws[RPB][8];
    const int wid = threadIdx.x >> 5;
    const int lid = threadIdx.x & 31;
    if (lid == 0) {
        #pragma unroll
        for (int r = 0; r < RPB; r++) ws[r][wid] = acc[r];
    }
    __syncthreads();

    // warp 0: 4 groups of 8 lanes, each group reduces one row
    if (wid == 0) {
        const int r  = lid >> 3;      // 0..3
        const int l8 = lid & 7;
        float s = ws[r][l8];
        s += __shfl_xor_sync(0xFFFFFFFFu, s, 4, 8);
        s += __shfl_xor_sync(0xFFFFFFFFu, s, 2, 8);
        s += __shfl_xor_sync(0xFFFFFFFFu, s, 1, 8);
        if (l8 == 0) pot[row0 + r] = s;
    }
}

extern "C" void kernel_launch(void* const* d_in, const int* in_sizes, int n_in,
                              void* d_out, int out_size) {
    const int*   x      = (const int*)  d_in[0];
    const float* weight = (const float*)d_in[1];
    const float* trace  = (const float*)d_in[2];
    const float* delay  = (const float*)d_in[3];
    const float* dinit  = (const float*)d_in[4];
    const float* dt_p   = (const float*)d_in[5];
    const float* tau_p  = (const float*)d_in[6];
    const float* alpha_p= (const float*)d_in[7];

    float* pot    = (float*)d_out;                 // (B,1,OUT) = 16384 floats
    float* folded = pot + (long)B_ * OUT_;         // (B,IN,OUT) flat = trace_new flat

    led_kernel<<<(B_ * OUT_) / RPB, 256>>>(x, weight, trace, delay, dinit,
                                           dt_p, tau_p, alpha_p, pot, folded);
}

// round 4
// speedup vs baseline: 1.0105x; 1.0105x over previous
#include <cuda_runtime.h>

// Problem constants
#define B_   16
#define OUT_ 1024
#define IN_  2048
#define WPB  8                        // warps per block = rows per block
#define NV4  (IN_ / 4)                // 512 float4 per row
#define ITER (NV4 / 32)               // 16 float4 per lane

__global__ __launch_bounds__(256)
void led_kernel(const int*   __restrict__ x,       // (B,1,IN) int32
                const float* __restrict__ weight,  // (OUT,IN)
                const float* __restrict__ trace,   // (B,OUT,IN)
                const float* __restrict__ delay,   // (B,OUT,IN)
                const float* __restrict__ dinit,   // constant tensor; only [0] read
                const float* __restrict__ dt_p,
                const float* __restrict__ tau_p,
                const float* __restrict__ alpha_p,
                float* __restrict__ pot,           // (B,OUT)
                float* __restrict__ folded)        // (B,OUT,IN) flat
{
    const int wid  = threadIdx.x >> 5;
    const int lane = threadIdx.x & 31;
    const int row  = blockIdx.x * WPB + wid;   // one warp per (b,o) row
    const int b    = row >> 10;                // / OUT_
    const int o    = row & (OUT_ - 1);

    const float k     = __ldg(dt_p) / __ldg(tau_p);
    const float alpha = __ldg(alpha_p);
    const float d0    = __ldg(dinit);          // constant-valued tensor
    const float c1    = 1.0f - k;              // t_new = c1*t + (k*alpha)*xf
    const float c0    = k * alpha;

    const long base = (long)row * IN_;
    const float4* __restrict__ tr4 = (const float4*)(trace  + base);
    const float4* __restrict__ dl4 = (const float4*)(delay  + base);
    const float4* __restrict__ w4  = (const float4*)(weight + (long)o * IN_);
    const int4*   __restrict__ x4  = (const int4*)  (x      + (long)b * IN_);
    float4*       __restrict__ ou4 = (float4*)(folded + base);

    float acc = 0.0f;

    #pragma unroll 4
    for (int i = 0; i < ITER; i++) {
        const int j = lane + (i << 5);

        float4 t  = __ldcs(tr4 + j);
        float4 d  = __ldcs(dl4 + j);
        float4 wv = __ldg (w4  + j);
        int4   xv = __ldg (x4  + j);

        const float xf0 = (float)xv.x, xf1 = (float)xv.y;
        const float xf2 = (float)xv.z, xf3 = (float)xv.w;

        // trace_new = (1-k)*t + (k*alpha)*x
        t.x = fmaf(c1, t.x, c0 * xf0);
        t.y = fmaf(c1, t.y, c0 * xf1);
        t.z = fmaf(c1, t.z, c0 * xf2);
        t.w = fmaf(c1, t.w, c0 * xf3);
        __stcs(ou4 + j, t);

        // spike ⇔ delay + d0*x == 1  ⇔  delay == 1 - d0*x  (exact integer floats)
        if (d.x == fmaf(-d0, xf0, 1.0f)) acc += wv.x;
        if (d.y == fmaf(-d0, xf1, 1.0f)) acc += wv.y;
        if (d.z == fmaf(-d0, xf2, 1.0f)) acc += wv.z;
        if (d.w == fmaf(-d0, xf3, 1.0f)) acc += wv.w;
    }

    // Warp-local reduction only — no smem, no __syncthreads.
    #pragma unroll
    for (int off = 16; off > 0; off >>= 1)
        acc += __shfl_xor_sync(0xFFFFFFFFu, acc, off);

    if (lane == 0) pot[row] = acc;
}

extern "C" void kernel_launch(void* const* d_in, const int* in_sizes, int n_in,
                              void* d_out, int out_size) {
    const int*   x      = (const int*)  d_in[0];
    const float* weight = (const float*)d_in[1];
    const float* trace  = (const float*)d_in[2];
    const float* delay  = (const float*)d_in[3];
    const float* dinit  = (const float*)d_in[4];
    const float* dt_p   = (const float*)d_in[5];
    const float* tau_p  = (const float*)d_in[6];
    const float* alpha_p= (const float*)d_in[7];

    float* pot    = (float*)d_out;                 // (B,1,OUT) = 16384 floats
    float* folded = pot + (long)B_ * OUT_;         // (B,IN,OUT) flat = trace_new flat

    led_kernel<<<(B_ * OUT_) / WPB, 256>>>(x, weight, trace, delay, dinit,
                                           dt_p, tau_p, alpha_p, pot, folded);
}

// round 5
// speedup vs baseline: 1.0598x; 1.0489x over previous
#include <cuda_runtime.h>

// Problem constants
#define B_   16
#define OUT_ 1024
#define IN_  2048
// One block per row; 512 threads; one float4 per thread per tensor.

__global__ __launch_bounds__(512)
void led_kernel(const int*   __restrict__ x,       // (B,1,IN) int32
                const float* __restrict__ weight,  // (OUT,IN)
                const float* __restrict__ trace,   // (B,OUT,IN)
                const float* __restrict__ delay,   // (B,OUT,IN)
                const float* __restrict__ dinit,   // constant tensor; only [0] read
                const float* __restrict__ dt_p,
                const float* __restrict__ tau_p,
                const float* __restrict__ alpha_p,
                float* __restrict__ pot,           // (B,OUT)
                float* __restrict__ folded)        // (B,OUT,IN) flat
{
    const int row = blockIdx.x;          // b*OUT + o
    const int b   = row >> 10;           // / OUT_
    const int o   = row & (OUT_ - 1);
    const int j   = threadIdx.x;         // 0..511 -> one float4

    const long base = (long)row * IN_;

    // Front-batched loads: 4 independent LDG.128
    const float4 t  = __ldcs((const float4*)(trace  + base) + j);
    const float4 d  = __ldcs((const float4*)(delay  + base) + j);
    const float4 wv = __ldg ((const float4*)(weight + (long)o * IN_) + j);
    const int4   xv = __ldg ((const int4*)  (x      + (long)b * IN_) + j);

    const float k     = __ldg(dt_p) / __ldg(tau_p);
    const float alpha = __ldg(alpha_p);
    const float d0    = __ldg(dinit);    // constant-valued tensor
    const float c1    = 1.0f - k;        // t_new = c1*t + (k*alpha)*x
    const float c0    = k * alpha;

    const float xf0 = (float)xv.x, xf1 = (float)xv.y;
    const float xf2 = (float)xv.z, xf3 = (float)xv.w;

    float4 tn;
    tn.x = fmaf(c1, t.x, c0 * xf0);
    tn.y = fmaf(c1, t.y, c0 * xf1);
    tn.z = fmaf(c1, t.z, c0 * xf2);
    tn.w = fmaf(c1, t.w, c0 * xf3);
    __stcs((float4*)(folded + base) + j, tn);

    // spike ⇔ delay + d0*x == 1  ⇔  delay == 1 - d0*x  (exact integer floats)
    float acc = 0.0f;
    if (d.x == fmaf(-d0, xf0, 1.0f)) acc += wv.x;
    if (d.y == fmaf(-d0, xf1, 1.0f)) acc += wv.y;
    if (d.z == fmaf(-d0, xf2, 1.0f)) acc += wv.z;
    if (d.w == fmaf(-d0, xf3, 1.0f)) acc += wv.w;

    // Warp reduce (5 shuffles)
    #pragma unroll
    for (int off = 16; off > 0; off >>= 1)
        acc += __shfl_xor_sync(0xFFFFFFFFu, acc, off);

    // Cross-warp: 16 warps
    __shared__ float ws[16];
    const int wid = j >> 5;
    const int lid = j & 31;
    if (lid == 0) ws[wid] = acc;
    __syncthreads();

    if (wid == 0) {
        float s = (lid < 16) ? ws[lid] : 0.0f;
        #pragma unroll
        for (int off = 8; off > 0; off >>= 1)
            s += __shfl_xor_sync(0xFFFFFFFFu, s, off);
        if (lid == 0) pot[row] = s;
    }
}

extern "C" void kernel_launch(void* const* d_in, const int* in_sizes, int n_in,
                              void* d_out, int out_size) {
    const int*   x      = (const int*)  d_in[0];
    const float* weight = (const float*)d_in[1];
    const float* trace  = (const float*)d_in[2];
    const float* delay  = (const float*)d_in[3];
    const float* dinit  = (const float*)d_in[4];
    const float* dt_p   = (const float*)d_in[5];
    const float* tau_p  = (const float*)d_in[6];
    const float* alpha_p= (const float*)d_in[7];

    float* pot    = (float*)d_out;                 // (B,1,OUT) = 16384 floats
    float* folded = pot + (long)B_ * OUT_;         // (B,IN,OUT) flat = trace_new flat

    led_kernel<<<B_ * OUT_, 512>>>(x, weight, trace, delay, dinit,
                                   dt_p, tau_p, alpha_p, pot, folded);
}

// round 6
// speedup vs baseline: 1.0981x; 1.0362x over previous
#include <cuda_runtime.h>

// Problem constants
#define B_   16
#define OUT_ 1024
#define IN_  2048

// Prologue: zero the pot region of d_out (poisoned to 0xAA by harness).
__global__ void zero_pot(float* __restrict__ pot) {
    pot[blockIdx.x * 256 + threadIdx.x] = 0.0f;   // 64 blocks x 256 = 16384
}

__global__ __launch_bounds__(256)
void led_kernel(const int*   __restrict__ x,       // (B,1,IN) int32
                const float* __restrict__ weight,  // (OUT,IN)
                const float* __restrict__ trace,   // (B,OUT,IN)
                const float* __restrict__ delay,   // (B,OUT,IN)
                const float* __restrict__ dinit,   // constant tensor; only [0] read
                const float* __restrict__ dt_p,
                const float* __restrict__ tau_p,
                const float* __restrict__ alpha_p,
                float* __restrict__ pot,           // (B,OUT), pre-zeroed
                float* __restrict__ folded)        // (B,OUT,IN) flat
{
    const int row = blockIdx.x;          // b*OUT + o
    const int b   = row >> 10;           // / OUT_
    const int o   = row & (OUT_ - 1);

    const float k     = __ldg(dt_p) / __ldg(tau_p);
    const float alpha = __ldg(alpha_p);
    const float d0    = __ldg(dinit);    // constant-valued tensor
    const float c1    = 1.0f - k;        // t_new = c1*t + (k*alpha)*x
    const float c0    = k * alpha;

    const long base = (long)row * IN_;
    const float4* __restrict__ tr4 = (const float4*)(trace  + base);
    const float4* __restrict__ dl4 = (const float4*)(delay  + base);
    const float4* __restrict__ w4  = (const float4*)(weight + (long)o * IN_);
    const int4*   __restrict__ x4  = (const int4*)  (x      + (long)b * IN_);
    float4* __restrict__ out4 = (float4*)(folded + base);

    const int j0 = threadIdx.x;
    const int j1 = threadIdx.x + 256;

    // Front-batch all loads (MLP). Streaming tensors use evict-first.
    float4 t0 = __ldcs(tr4 + j0);
    float4 t1 = __ldcs(tr4 + j1);
    float4 dA = __ldcs(dl4 + j0);
    float4 dB = __ldcs(dl4 + j1);
    float4 w0 = __ldg (w4  + j0);
    float4 w1 = __ldg (w4  + j1);
    int4   xA = __ldg (x4  + j0);
    int4   xB = __ldg (x4  + j1);

    float acc = 0.0f;

    // ---- iter 0 ----
    {
        float xf0 = (float)xA.x, xf1 = (float)xA.y, xf2 = (float)xA.z, xf3 = (float)xA.w;

        t0.x = fmaf(c1, t0.x, c0 * xf0);
        t0.y = fmaf(c1, t0.y, c0 * xf1);
        t0.z = fmaf(c1, t0.z, c0 * xf2);
        t0.w = fmaf(c1, t0.w, c0 * xf3);
        __stcs(out4 + j0, t0);

        // spike ⇔ delay == 1 - d0*x   (exact integer-valued floats)
        if (dA.x == fmaf(-d0, xf0, 1.0f)) acc += w0.x;
        if (dA.y == fmaf(-d0, xf1, 1.0f)) acc += w0.y;
        if (dA.z == fmaf(-d0, xf2, 1.0f)) acc += w0.z;
        if (dA.w == fmaf(-d0, xf3, 1.0f)) acc += w0.w;
    }
    // ---- iter 1 ----
    {
        float xf0 = (float)xB.x, xf1 = (float)xB.y, xf2 = (float)xB.z, xf3 = (float)xB.w;

        t1.x = fmaf(c1, t1.x, c0 * xf0);
        t1.y = fmaf(c1, t1.y, c0 * xf1);
        t1.z = fmaf(c1, t1.z, c0 * xf2);
        t1.w = fmaf(c1, t1.w, c0 * xf3);
        __stcs(out4 + j1, t1);

        if (dB.x == fmaf(-d0, xf0, 1.0f)) acc += w1.x;
        if (dB.y == fmaf(-d0, xf1, 1.0f)) acc += w1.y;
        if (dB.z == fmaf(-d0, xf2, 1.0f)) acc += w1.z;
        if (dB.w == fmaf(-d0, xf3, 1.0f)) acc += w1.w;
    }

    // Warp reduce, then one fire-and-forget atomic per warp (8 per row).
    #pragma unroll
    for (int off = 16; off > 0; off >>= 1)
        acc += __shfl_xor_sync(0xFFFFFFFFu, acc, off);

    if ((threadIdx.x & 31) == 0)
        atomicAdd(pot + row, acc);
}

extern "C" void kernel_launch(void* const* d_in, const int* in_sizes, int n_in,
                              void* d_out, int out_size) {
    const int*   x      = (const int*)  d_in[0];
    const float* weight = (const float*)d_in[1];
    const float* trace  = (const float*)d_in[2];
    const float* delay  = (const float*)d_in[3];
    const float* dinit  = (const float*)d_in[4];
    const float* dt_p   = (const float*)d_in[5];
    const float* tau_p  = (const float*)d_in[6];
    const float* alpha_p= (const float*)d_in[7];

    float* pot    = (float*)d_out;                 // (B,1,OUT) = 16384 floats
    float* folded = pot + (long)B_ * OUT_;         // (B,IN,OUT) flat = trace_new flat

    zero_pot<<<(B_ * OUT_) / 256, 256>>>(pot);
    led_kernel<<<B_ * OUT_, 256>>>(x, weight, trace, delay, dinit,
                                   dt_p, tau_p, alpha_p, pot, folded);
}